// round 1
// baseline (speedup 1.0000x reference)
#include <cuda_runtime.h>
#include <cstdint>

#define B_Q   256
#define D_DIM 256
#define NMEM  500000
#define K_NN  64
#define C_CLS 50

// ---------------- scratch (device globals: no allocation allowed) -------------
__device__ float g_sims[(size_t)B_Q * NMEM];   // 512 MB
__device__ float g_qe[B_Q * D_DIM];
__device__ float g_qt[B_Q * D_DIM];
__device__ int   g_topk[B_Q * K_NN];

// ---------------- helpers ----------------------------------------------------
__device__ __forceinline__ unsigned long long pack2(float x, float y) {
    unsigned long long r;
    asm("mov.b64 %0, {%1, %2};" : "=l"(r) : "f"(x), "f"(y));
    return r;
}
__device__ __forceinline__ void unpack2(unsigned long long v, float& x, float& y) {
    asm("mov.b64 {%0, %1}, %2;" : "=f"(x), "=f"(y) : "l"(v));
}
__device__ __forceinline__ void ffma2(unsigned long long& c, unsigned long long a,
                                      unsigned long long b) {
    asm("fma.rn.f32x2 %0, %1, %2, %0;" : "+l"(c) : "l"(a), "l"(b));
}
__device__ __forceinline__ unsigned int fkey(float f) {
    unsigned int u = __float_as_uint(f);
    return (u & 0x80000000u) ? ~u : (u | 0x80000000u);
}

// ---------------- kernel 1: qe = relu(query); qt = relu(qe @ Wd^T + bd) -------
__global__ void prep_kernel(const float* __restrict__ query,
                            const float* __restrict__ Wd,
                            const float* __restrict__ bd) {
    int b = blockIdx.x, tid = threadIdx.x;
    __shared__ float qs[D_DIM];
    float q = fmaxf(query[b * D_DIM + tid], 0.f);
    qs[tid] = q;
    g_qe[b * D_DIM + tid] = q;
    __syncthreads();
    const float4* w4 = (const float4*)(Wd + tid * D_DIM);
    const float4* q4 = (const float4*)qs;
    float acc = bd[tid];
#pragma unroll 8
    for (int i = 0; i < D_DIM / 4; i++) {
        float4 a = q4[i], w = w4[i];
        acc += a.x * w.x + a.y * w.y + a.z * w.z + a.w * w.w;
    }
    g_qt[b * D_DIM + tid] = fmaxf(acc, 0.f);
}

// ---------------- kernel 2: sims[m][n] = dot(qe[m], mk[n]) / max(||mk[n]||,eps)
// 128x128 tile, BK=16, 8x8 per thread, fp32x2 packed FFMA, fused row-norm.
__global__ __launch_bounds__(256) void gemm_kernel(const float* __restrict__ Bm) {
    __shared__ float As[16][128];
    __shared__ float Bs[16][128];
    __shared__ float invn[128];

    const int tid = threadIdx.x;
    const int n0 = blockIdx.x * 128;
    const int m0 = blockIdx.y * 128;
    const int lr = tid >> 1;            // row (0..127) this thread loads
    const int lc = (tid & 1) * 8;       // col offset (0 or 8)
    const int tx = tid & 15;            // n-dir thread coord
    const int ty = tid >> 4;            // m-dir thread coord

    const bool full   = (n0 + 128 <= NMEM);
    const bool bvalid = (n0 + lr < NMEM);
    const float* Aload = g_qe + (m0 + lr) * D_DIM + lc;
    const float* Bload = Bm + (size_t)(bvalid ? (n0 + lr) : 0) * D_DIM + lc;

    unsigned long long c2[8][4];
#pragma unroll
    for (int i = 0; i < 8; i++)
#pragma unroll
        for (int j = 0; j < 4; j++) c2[i][j] = 0ull;

    float ssq = 0.f;

    for (int kt = 0; kt < D_DIM; kt += 16) {
        float4 a0 = *(const float4*)(Aload + kt);
        float4 a1 = *(const float4*)(Aload + kt + 4);
        float4 b0 = make_float4(0.f, 0.f, 0.f, 0.f), b1 = b0;
        if (bvalid) {
            b0 = *(const float4*)(Bload + kt);
            b1 = *(const float4*)(Bload + kt + 4);
        }
        ssq += b0.x * b0.x + b0.y * b0.y + b0.z * b0.z + b0.w * b0.w +
               b1.x * b1.x + b1.y * b1.y + b1.z * b1.z + b1.w * b1.w;

        __syncthreads();   // prior-iter readers done
        As[lc + 0][lr] = a0.x; As[lc + 1][lr] = a0.y; As[lc + 2][lr] = a0.z; As[lc + 3][lr] = a0.w;
        As[lc + 4][lr] = a1.x; As[lc + 5][lr] = a1.y; As[lc + 6][lr] = a1.z; As[lc + 7][lr] = a1.w;
        Bs[lc + 0][lr] = b0.x; Bs[lc + 1][lr] = b0.y; Bs[lc + 2][lr] = b0.z; Bs[lc + 3][lr] = b0.w;
        Bs[lc + 4][lr] = b1.x; Bs[lc + 5][lr] = b1.y; Bs[lc + 6][lr] = b1.z; Bs[lc + 7][lr] = b1.w;
        __syncthreads();

#pragma unroll
        for (int kk = 0; kk < 16; kk++) {
            float4 av0 = *(const float4*)&As[kk][ty * 8];
            float4 av1 = *(const float4*)&As[kk][ty * 8 + 4];
            double2 bd0 = *(const double2*)&Bs[kk][tx * 8];
            double2 bd1 = *(const double2*)&Bs[kk][tx * 8 + 4];
            unsigned long long bp[4];
            bp[0] = __double_as_longlong(bd0.x);
            bp[1] = __double_as_longlong(bd0.y);
            bp[2] = __double_as_longlong(bd1.x);
            bp[3] = __double_as_longlong(bd1.y);
            float af[8] = {av0.x, av0.y, av0.z, av0.w, av1.x, av1.y, av1.z, av1.w};
#pragma unroll
            for (int i = 0; i < 8; i++) {
                unsigned long long ap = pack2(af[i], af[i]);
#pragma unroll
                for (int j = 0; j < 4; j++) ffma2(c2[i][j], ap, bp[j]);
            }
        }
    }

    // fused inverse norm for the 128 B-rows of this tile
    float ss2 = ssq + __shfl_xor_sync(0xffffffffu, ssq, 1);
    if ((tid & 1) == 0) invn[lr] = 1.f / fmaxf(sqrtf(ss2), 1e-8f);
    __syncthreads();

    float inv[8];
#pragma unroll
    for (int j = 0; j < 8; j++) inv[j] = invn[tx * 8 + j];

#pragma unroll
    for (int i = 0; i < 8; i++) {
        int m = m0 + ty * 8 + i;
        float v[8];
#pragma unroll
        for (int j = 0; j < 4; j++) unpack2(c2[i][j], v[2 * j], v[2 * j + 1]);
#pragma unroll
        for (int j = 0; j < 8; j++) v[j] *= inv[j];
        float* orow = g_sims + (size_t)m * NMEM + n0 + tx * 8;
        if (full) {
            *(float4*)orow       = make_float4(v[0], v[1], v[2], v[3]);
            *(float4*)(orow + 4) = make_float4(v[4], v[5], v[6], v[7]);
        } else {
#pragma unroll
            for (int j = 0; j < 8; j++)
                if (n0 + tx * 8 + j < NMEM) orow[j] = v[j];
        }
    }
}

// ---------------- kernel 3: exact per-row top-64 (radix-bin select) -----------
#define TK_CAP 2048
__global__ void topk_kernel() {
    const int row = blockIdx.x, tid = threadIdx.x;
    __shared__ unsigned int hist[2048];
    __shared__ float cval[TK_CAP];
    __shared__ int cidx[TK_CAP];
    __shared__ int s_t, s_chi, s_m, out_cnt, cand_cnt;
    __shared__ float rv[256];
    __shared__ int ri[256];

    for (int i = tid; i < 2048; i += 256) hist[i] = 0u;
    if (tid == 0) { out_cnt = 0; cand_cnt = 0; }
    __syncthreads();

    const float* srow = g_sims + (size_t)row * NMEM;
    for (int i = tid; i < NMEM; i += 256)
        atomicAdd(&hist[fkey(srow[i]) >> 21], 1u);
    __syncthreads();

    if (tid == 0) {
        int c = 0, t = 2047;
        for (; t >= 0; --t) {
            int nc = c + (int)hist[t];
            if (nc >= K_NN) break;
            c = nc;
        }
        s_t = t; s_chi = c; s_m = K_NN - c;
    }
    __syncthreads();
    const int t = s_t;

    for (int i = tid; i < NMEM; i += 256) {
        float v = srow[i];
        int b = (int)(fkey(v) >> 21);
        if (b > t) {
            int p = atomicAdd(&out_cnt, 1);
            g_topk[row * K_NN + p] = i;
        } else if (b == t) {
            int c = atomicAdd(&cand_cnt, 1);
            if (c < TK_CAP) { cval[c] = v; cidx[c] = i; }
        }
    }
    __syncthreads();

    const int nc = min(cand_cnt, TK_CAP);
    const int m = s_m;
    for (int r = 0; r < m; r++) {
        float bv = -3.0e38f; int bi = -1;
        for (int i = tid; i < nc; i += 256)
            if (cval[i] > bv) { bv = cval[i]; bi = i; }
        rv[tid] = bv; ri[tid] = bi;
        __syncthreads();
        for (int s = 128; s > 0; s >>= 1) {
            if (tid < s && rv[tid + s] > rv[tid]) { rv[tid] = rv[tid + s]; ri[tid] = ri[tid + s]; }
            __syncthreads();
        }
        if (tid == 0) {
            int w = ri[0];
            g_topk[row * K_NN + s_chi + r] = cidx[w];
            cval[w] = -3.0e38f;
        }
        __syncthreads();
    }
}

// ---------------- kernel 4: attention + layernorm + classifier ----------------
__global__ void tail_kernel(const float* __restrict__ mk,
                            const float* __restrict__ Wc,
                            const float* __restrict__ bc,
                            const float* __restrict__ gamma,
                            const float* __restrict__ beta,
                            float* __restrict__ out) {
    const int b = blockIdx.x, tid = threadIdx.x;
    const int wid = tid >> 5, lane = tid & 31;
    __shared__ float qe_s[D_DIM], qt_s[D_DIM], sc[K_NN], wgt[K_NN];
    __shared__ int idxs[K_NN];
    __shared__ float merged[2 * D_DIM];
    __shared__ float red[256];

    qe_s[tid] = g_qe[b * D_DIM + tid];
    qt_s[tid] = g_qt[b * D_DIM + tid];
    if (tid < K_NN) idxs[tid] = g_topk[b * K_NN + tid];
    __syncthreads();

    // scores[j] = dot(qt, mk[idx_j])
    for (int j = wid; j < K_NN; j += 8) {
        const float* r = mk + (size_t)idxs[j] * D_DIM;
        float p = 0.f;
#pragma unroll
        for (int i = 0; i < 8; i++) p += qt_s[lane + 32 * i] * r[lane + 32 * i];
        for (int o = 16; o > 0; o >>= 1) p += __shfl_xor_sync(0xffffffffu, p, o);
        if (lane == 0) sc[j] = p;
    }
    __syncthreads();

    // softmax over 64 (warp 0)
    if (wid == 0) {
        float v0 = sc[lane], v1 = sc[lane + 32];
        float mx = fmaxf(v0, v1);
        for (int o = 16; o > 0; o >>= 1) mx = fmaxf(mx, __shfl_xor_sync(0xffffffffu, mx, o));
        float e0 = expf(v0 - mx), e1 = expf(v1 - mx);
        float s = e0 + e1;
        for (int o = 16; o > 0; o >>= 1) s += __shfl_xor_sync(0xffffffffu, s, o);
        float is = 1.f / s;
        wgt[lane] = e0 * is;
        wgt[lane + 32] = e1 * is;
    }
    __syncthreads();

    // attended[d] + residual
    float acc = 0.f;
    for (int j = 0; j < K_NN; j++)
        acc += wgt[j] * mk[(size_t)idxs[j] * D_DIM + tid];
    float r = acc + qe_s[tid];

    // layernorm
    red[tid] = r;
    __syncthreads();
    for (int s = 128; s > 0; s >>= 1) {
        if (tid < s) red[tid] += red[tid + s];
        __syncthreads();
    }
    float mu = red[0] / (float)D_DIM;
    __syncthreads();
    float d = r - mu;
    red[tid] = d * d;
    __syncthreads();
    for (int s = 128; s > 0; s >>= 1) {
        if (tid < s) red[tid] += red[tid + s];
        __syncthreads();
    }
    float var = red[0] / (float)D_DIM;
    float y = d * rsqrtf(var + 1e-5f) * gamma[tid] + beta[tid];

    merged[tid] = qe_s[tid];
    merged[D_DIM + tid] = y;
    __syncthreads();

    // classifier: out[b][c] = merged . Wc[c] + bc[c]
    for (int c = wid; c < C_CLS; c += 8) {
        const float* wr = Wc + c * 2 * D_DIM;
        float p = 0.f;
#pragma unroll
        for (int i = 0; i < 16; i++) p += merged[lane + 32 * i] * wr[lane + 32 * i];
        for (int o = 16; o > 0; o >>= 1) p += __shfl_xor_sync(0xffffffffu, p, o);
        if (lane == 0) out[b * C_CLS + c] = p + bc[c];
    }
}

// ---------------- launch ------------------------------------------------------
extern "C" void kernel_launch(void* const* d_in, const int* in_sizes, int n_in,
                              void* d_out, int out_size) {
    const float* query = (const float*)d_in[0];
    const float* mk    = (const float*)d_in[1];
    const float* Wd    = (const float*)d_in[2];
    const float* bd    = (const float*)d_in[3];
    const float* gamma = (const float*)d_in[4];
    const float* beta  = (const float*)d_in[5];
    const float* Wc    = (const float*)d_in[6];
    const float* bc    = (const float*)d_in[7];
    float* out = (float*)d_out;

    prep_kernel<<<B_Q, 256>>>(query, Wd, bd);
    dim3 g((NMEM + 127) / 128, B_Q / 128);
    gemm_kernel<<<g, 256>>>(mk);
    topk_kernel<<<B_Q, 256>>>();
    tail_kernel<<<B_Q, 256>>>(mk, Wc, bc, gamma, beta, out);
}

// round 6
// speedup vs baseline: 3.1246x; 3.1246x over previous
#include <cuda_runtime.h>
#include <cuda_bf16.h>
#include <cstdint>

#define B_Q    256
#define D_DIM  256
#define NMEM   500000
#define K_NN   64
#define C_CLS  50
#define NTILES 3907          // ceil(500000/128)
#define CT_CAP 1024
#define CE_CAP 4096

// ---------------- device scratch (no allocation allowed) ---------------------
__device__ unsigned short g_keys[(size_t)B_Q * NMEM];     // 256 MB monotone bf16 keys
__device__ unsigned short g_tmax[(size_t)B_Q * NTILES];   // per (row, tile) max key
__device__ int   g_ctiles[B_Q * CT_CAP];
__device__ int   g_ctilecnt[B_Q];
__device__ int   g_tau[B_Q];
__device__ float g_qe[B_Q * D_DIM];
__device__ float g_qt[B_Q * D_DIM];
__device__ int   g_topk[B_Q * K_NN];
__device__ __nv_bfloat162 g_A[B_Q * D_DIM / 2];           // qe in bf16, row-major

// ---------------- helpers ----------------------------------------------------
__device__ __forceinline__ uint32_t smem_u32(const void* p) {
    uint32_t a;
    asm("{ .reg .u64 t; cvta.to.shared.u64 t, %1; cvt.u32.u64 %0, t; }" : "=r"(a) : "l"(p));
    return a;
}
__device__ __forceinline__ void ldsm4(uint32_t& r0, uint32_t& r1, uint32_t& r2,
                                      uint32_t& r3, uint32_t addr) {
    asm volatile("ldmatrix.sync.aligned.m8n8.x4.shared.b16 {%0,%1,%2,%3}, [%4];"
                 : "=r"(r0), "=r"(r1), "=r"(r2), "=r"(r3) : "r"(addr));
}
__device__ __forceinline__ void mma16816(float* c, const uint32_t* a, const uint32_t* b) {
    asm volatile(
        "mma.sync.aligned.m16n8k16.row.col.f32.bf16.bf16.f32 "
        "{%0,%1,%2,%3}, {%4,%5,%6,%7}, {%8,%9}, {%0,%1,%2,%3};"
        : "+f"(c[0]), "+f"(c[1]), "+f"(c[2]), "+f"(c[3])
        : "r"(a[0]), "r"(a[1]), "r"(a[2]), "r"(a[3]), "r"(b[0]), "r"(b[1]));
}
__device__ __forceinline__ unsigned short tokey(float v) {
    unsigned short u = __bfloat16_as_ushort(__float2bfloat16(v));
    return (u & 0x8000) ? (unsigned short)(~u) : (unsigned short)(u | 0x8000);
}

// ---------------- kernel 1: qe, qt, bf16 A ------------------------------------
__global__ void prep_kernel(const float* __restrict__ query,
                            const float* __restrict__ Wd,
                            const float* __restrict__ bd) {
    int b = blockIdx.x, tid = threadIdx.x;
    __shared__ float qs[D_DIM];
    float q = fmaxf(query[b * D_DIM + tid], 0.f);
    qs[tid] = q;
    g_qe[b * D_DIM + tid] = q;
    __syncthreads();

    if (tid < 128)
        g_A[b * 128 + tid] = __float22bfloat162_rn(make_float2(qs[2 * tid], qs[2 * tid + 1]));

    const float4* w4 = (const float4*)(Wd + tid * D_DIM);
    const float4* q4 = (const float4*)qs;
    float acc = bd[tid];
#pragma unroll 8
    for (int i = 0; i < D_DIM / 4; i++) {
        float4 a = q4[i], w = w4[i];
        acc += a.x * w.x + a.y * w.y + a.z * w.z + a.w * w.w;
    }
    g_qt[b * D_DIM + tid] = fmaxf(acc, 0.f);
}

// ---------------- kernel 2: bf16 HMMA GEMM + key epilogue ---------------------
// smem layout (bytes):
//   [0, 512)           invn[128] fp32
//   [512, 136192)      A  : 256 rows x 528 B pitch (264 bf16)   [stage reuses this]
//   [136192, 203776)   B  : 128 rows x 528 B pitch
#define SM_INV  0
#define SM_AOFF 512
#define APITCH  528
#define SM_BOFF 136192
#define SM_TOT  203776
#define STPITCH 272   // stage: 256 rows x 272 B (136 u16)

__global__ void __launch_bounds__(256, 1)
gemm_kernel(const float* __restrict__ mk) {
    extern __shared__ char smem[];
    const uint32_t sb = smem_u32(smem);
    float* invn_s = (float*)(smem + SM_INV);
    const int tid = threadIdx.x;
    const int wid = tid >> 5, lane = tid & 31;
    const int bx = blockIdx.x;
    const int n0 = bx * 128;

    // ---- A: g_A (bf16 row-major, L2-resident) -> smem pitch 528 ----
    {
        const uint4* src = (const uint4*)g_A;
#pragma unroll
        for (int i = 0; i < 32; i++) {
            int row = i * 8 + wid;
            *(uint4*)(smem + SM_AOFF + row * APITCH + lane * 16) = src[row * 32 + lane];
        }
    }

    // ---- B: fp32 global -> bf16 smem pitch 528, fused row sumsq ----
    {
#pragma unroll
        for (int i = 0; i < 16; i++) {
            int r = i * 8 + wid;          // warp owns row r this iter
            int n = n0 + r;
            float4 v0 = make_float4(0.f, 0.f, 0.f, 0.f), v1 = v0;
            if (n < NMEM) {
                const float* rp = mk + (size_t)n * D_DIM + lane * 8;
                v0 = *(const float4*)rp;
                v1 = *(const float4*)(rp + 4);
            }
            float s = v0.x * v0.x + v0.y * v0.y + v0.z * v0.z + v0.w * v0.w
                    + v1.x * v1.x + v1.y * v1.y + v1.z * v1.z + v1.w * v1.w;
#pragma unroll
            for (int o = 16; o > 0; o >>= 1) s += __shfl_xor_sync(0xffffffffu, s, o);
            if (lane == 0) invn_s[r] = s;
            __nv_bfloat162 p0 = __float22bfloat162_rn(make_float2(v0.x, v0.y));
            __nv_bfloat162 p1 = __float22bfloat162_rn(make_float2(v0.z, v0.w));
            __nv_bfloat162 p2 = __float22bfloat162_rn(make_float2(v1.x, v1.y));
            __nv_bfloat162 p3 = __float22bfloat162_rn(make_float2(v1.z, v1.w));
            *(uint4*)(smem + SM_BOFF + r * APITCH + lane * 16) =
                make_uint4(*(uint32_t*)&p0, *(uint32_t*)&p1, *(uint32_t*)&p2, *(uint32_t*)&p3);
        }
    }
    __syncthreads();
    if (tid < 128) invn_s[tid] = 1.f / fmaxf(sqrtf(invn_s[tid]), 1e-8f);
    __syncthreads();

    // ---- MMA mainloop: warp grid 4(M) x 2(N); 64x64 per warp ----
    const int wm = wid >> 1, wn = wid & 1;
    const int m_base = wm * 64, n_base = wn * 64;

    float acc[4][8][4];
#pragma unroll
    for (int mi = 0; mi < 4; mi++)
#pragma unroll
        for (int nj = 0; nj < 8; nj++)
#pragma unroll
            for (int r = 0; r < 4; r++) acc[mi][nj][r] = 0.f;

    // per-lane ldmatrix offsets
    const int a_row = ((lane >> 3) & 1) * 8 + (lane & 7);
    const int a_col = (lane >> 4) * 8;
    const int b_row = (lane >> 4) * 8 + (lane & 7);
    const int b_col = ((lane >> 3) & 1) * 8;

    uint32_t pa[4], pb[4];
#pragma unroll
    for (int mi = 0; mi < 4; mi++)
        pa[mi] = sb + SM_AOFF + (m_base + mi * 16 + a_row) * APITCH + a_col * 2;
#pragma unroll
    for (int nb = 0; nb < 4; nb++)
        pb[nb] = sb + SM_BOFF + (n_base + nb * 16 + b_row) * APITCH + b_col * 2;

#pragma unroll 2
    for (int ks = 0; ks < 16; ks++) {
        const int koff = ks * 32;    // 16 bf16 = 32 bytes
        uint32_t af[4][4], bf[4][4];
#pragma unroll
        for (int mi = 0; mi < 4; mi++)
            ldsm4(af[mi][0], af[mi][1], af[mi][2], af[mi][3], pa[mi] + koff);
#pragma unroll
        for (int nb = 0; nb < 4; nb++)
            ldsm4(bf[nb][0], bf[nb][1], bf[nb][2], bf[nb][3], pb[nb] + koff);
#pragma unroll
        for (int mi = 0; mi < 4; mi++)
#pragma unroll
            for (int nj = 0; nj < 8; nj++)
                mma16816(acc[mi][nj], af[mi], &bf[nj >> 1][(nj & 1) * 2]);
    }

    __syncthreads();   // done reading A/B smem

    // ---- stage keys in smem (reuse A region): rows m 0..255, cols n 0..127 ----
    {
        char* stage = smem + SM_AOFF;
#pragma unroll
        for (int mi = 0; mi < 4; mi++) {
#pragma unroll
            for (int nj = 0; nj < 8; nj++) {
                int nl = n_base + nj * 8 + (lane & 3) * 2;
                int ng = n0 + nl;
                float i0 = invn_s[nl], i1 = invn_s[nl + 1];
                int m0 = m_base + mi * 16 + (lane >> 2);
#pragma unroll
                for (int g = 0; g < 2; g++) {
                    int m = m0 + g * 8;
                    unsigned short k0 = 0, k1 = 0;
                    if (ng < NMEM)     k0 = tokey(acc[mi][nj][2 * g] * i0);
                    if (ng + 1 < NMEM) k1 = tokey(acc[mi][nj][2 * g + 1] * i1);
                    *(uint32_t*)(stage + m * STPITCH + nl * 2) =
                        (uint32_t)k0 | ((uint32_t)k1 << 16);
                }
            }
        }
    }
    __syncthreads();

    // ---- coalesced global write + per-(row, tile) max : 2 threads per row,
    //      each thread handles TWO rows (256 rows total) ----
    {
        const char* stage = smem + SM_AOFF;
        const int part = tid & 1;
#pragma unroll
        for (int half = 0; half < 2; half++) {
            const int m = (tid >> 1) + half * 128;
            const unsigned short* srow = (const unsigned short*)(stage + m * STPITCH);
            unsigned short* drow = g_keys + (size_t)m * NMEM + n0;
            uint32_t kmax = 0;
#pragma unroll
            for (int i = 0; i < 8; i++) {
                int c = (i * 2 + part) * 8;             // u16 col of this 16B chunk
                uint4 v = *(const uint4*)(srow + c);
                const unsigned short* u = (const unsigned short*)&v;
#pragma unroll
                for (int j = 0; j < 8; j++) kmax = max(kmax, (uint32_t)u[j]);
                if (n0 + c + 8 <= NMEM) *(uint4*)(drow + c) = v;
            }
            uint32_t other = __shfl_xor_sync(0xffffffffu, kmax, 1);
            kmax = max(kmax, other);
            if (part == 0) g_tmax[(size_t)m * NTILES + bx] = (unsigned short)kmax;
        }
    }
}

// ---------------- kernel 3: per-row threshold + candidate tiles ---------------
__global__ void thresh_kernel() {
    const int row = blockIdx.x, tid = threadIdx.x;
    __shared__ uint32_t hist[4096];
    __shared__ uint32_t bsum[256];
    __shared__ int s_tau, s_cnt;
    for (int i = tid; i < 4096; i += 256) hist[i] = 0;
    if (tid == 0) s_cnt = 0;
    __syncthreads();

    const unsigned short* tm = g_tmax + (size_t)row * NTILES;
    for (int i = tid; i < NTILES; i += 256)
        atomicAdd(&hist[tm[i] >> 4], 1u);
    __syncthreads();

    uint32_t bs = 0;
#pragma unroll
    for (int j = 0; j < 16; j++) bs += hist[tid * 16 + j];
    bsum[tid] = bs;
    __syncthreads();

    if (tid == 0) {
        int cum = 0, tau = 0;
        for (int b = 255; b >= 0; b--) {
            if (cum + (int)bsum[b] >= K_NN) {
                for (int bin = b * 16 + 15; bin >= b * 16; bin--) {
                    cum += (int)hist[bin];
                    if (cum >= K_NN) { tau = bin - 1; break; }
                }
                break;
            }
            cum += (int)bsum[b];
        }
        if (tau < 0) tau = 0;
        s_tau = tau;
        g_tau[row] = tau;
    }
    __syncthreads();
    const int tau = s_tau;

    for (int i = tid; i < NTILES; i += 256) {
        if ((int)(tm[i] >> 4) >= tau) {
            int p = atomicAdd(&s_cnt, 1);
            if (p < CT_CAP) g_ctiles[row * CT_CAP + p] = i;
        }
    }
    __syncthreads();
    if (tid == 0) g_ctilecnt[row] = min(s_cnt, CT_CAP);
}

// ---------------- kernel 4: gather + exact fp32 rescore + exact top-64 --------
__global__ void select_kernel(const float* __restrict__ mk) {
    const int row = blockIdx.x, tid = threadIdx.x;
    const int wid = tid >> 5, lane = tid & 31;
    __shared__ int   cidx[CE_CAP];
    __shared__ float cval[CE_CAP];
    __shared__ float qe_s[D_DIM];
    __shared__ float rv[256];
    __shared__ int   rp[256];
    __shared__ int   s_cnt;

    if (tid == 0) s_cnt = 0;
    qe_s[tid] = g_qe[row * D_DIM + tid];
    __syncthreads();

    const int tau = g_tau[row];
    const int tcnt = g_ctilecnt[row];
    const unsigned short* keys = g_keys + (size_t)row * NMEM;

    for (int p = tid; p < tcnt * 128; p += 256) {
        int t = g_ctiles[row * CT_CAP + (p >> 7)];
        int n = t * 128 + (p & 127);
        if (n < NMEM && (int)(keys[n] >> 4) >= tau) {
            int q = atomicAdd(&s_cnt, 1);
            if (q < CE_CAP) cidx[q] = n;
        }
    }
    __syncthreads();
    const int nc = min(s_cnt, CE_CAP);

    // exact fp32 cosine rescore (query norm omitted: positive row constant)
    for (int c = wid; c < nc; c += 8) {
        const float* r = mk + (size_t)cidx[c] * D_DIM;
        float d = 0.f, s = 0.f;
#pragma unroll
        for (int i = 0; i < 8; i++) {
            float x = r[lane + 32 * i];
            d += qe_s[lane + 32 * i] * x;
            s += x * x;
        }
#pragma unroll
        for (int o = 16; o > 0; o >>= 1) {
            d += __shfl_xor_sync(0xffffffffu, d, o);
            s += __shfl_xor_sync(0xffffffffu, s, o);
        }
        if (lane == 0) cval[c] = d / fmaxf(sqrtf(s), 1e-8f);
    }
    __syncthreads();

    // exact top-64 (value desc, tie -> lower memory index)
    for (int r = 0; r < K_NN; r++) {
        float bv = -3.0e38f; int bp = -1;
        for (int i = tid; i < nc; i += 256) {
            float v = cval[i];
            if (v > bv || (v == bv && bp >= 0 && cidx[i] < cidx[bp])) { bv = v; bp = i; }
        }
        rv[tid] = bv; rp[tid] = bp;
        __syncthreads();
        for (int s = 128; s > 0; s >>= 1) {
            if (tid < s) {
                float v2 = rv[tid + s]; int p2 = rp[tid + s];
                bool take = (v2 > rv[tid]) ||
                            (v2 == rv[tid] && p2 >= 0 &&
                             (rp[tid] < 0 || cidx[p2] < cidx[rp[tid]]));
                if (take) { rv[tid] = v2; rp[tid] = p2; }
            }
            __syncthreads();
        }
        if (tid == 0) {
            int w = rp[0];
            g_topk[row * K_NN + r] = cidx[w];
            cval[w] = -3.0e38f;
        }
        __syncthreads();
    }
}

// ---------------- kernel 5: attention + layernorm + classifier ----------------
__global__ void tail_kernel(const float* __restrict__ mk,
                            const float* __restrict__ Wc,
                            const float* __restrict__ bc,
                            const float* __restrict__ gamma,
                            const float* __restrict__ beta,
                            float* __restrict__ out) {
    const int b = blockIdx.x, tid = threadIdx.x;
    const int wid = tid >> 5, lane = tid & 31;
    __shared__ float qe_s[D_DIM], qt_s[D_DIM], sc[K_NN], wgt[K_NN];
    __shared__ int idxs[K_NN];
    __shared__ float merged[2 * D_DIM];
    __shared__ float red[256];

    qe_s[tid] = g_qe[b * D_DIM + tid];
    qt_s[tid] = g_qt[b * D_DIM + tid];
    if (tid < K_NN) idxs[tid] = g_topk[b * K_NN + tid];
    __syncthreads();

    for (int j = wid; j < K_NN; j += 8) {
        const float* r = mk + (size_t)idxs[j] * D_DIM;
        float p = 0.f;
#pragma unroll
        for (int i = 0; i < 8; i++) p += qt_s[lane + 32 * i] * r[lane + 32 * i];
        for (int o = 16; o > 0; o >>= 1) p += __shfl_xor_sync(0xffffffffu, p, o);
        if (lane == 0) sc[j] = p;
    }
    __syncthreads();

    if (wid == 0) {
        float v0 = sc[lane], v1 = sc[lane + 32];
        float mx = fmaxf(v0, v1);
        for (int o = 16; o > 0; o >>= 1) mx = fmaxf(mx, __shfl_xor_sync(0xffffffffu, mx, o));
        float e0 = expf(v0 - mx), e1 = expf(v1 - mx);
        float s = e0 + e1;
        for (int o = 16; o > 0; o >>= 1) s += __shfl_xor_sync(0xffffffffu, s, o);
        float is = 1.f / s;
        wgt[lane] = e0 * is;
        wgt[lane + 32] = e1 * is;
    }
    __syncthreads();

    float acc = 0.f;
    for (int j = 0; j < K_NN; j++)
        acc += wgt[j] * mk[(size_t)idxs[j] * D_DIM + tid];
    float r = acc + qe_s[tid];

    red[tid] = r;
    __syncthreads();
    for (int s = 128; s > 0; s >>= 1) {
        if (tid < s) red[tid] += red[tid + s];
        __syncthreads();
    }
    float mu = red[0] / (float)D_DIM;
    __syncthreads();
    float d = r - mu;
    red[tid] = d * d;
    __syncthreads();
    for (int s = 128; s > 0; s >>= 1) {
        if (tid < s) red[tid] += red[tid + s];
        __syncthreads();
    }
    float var = red[0] / (float)D_DIM;
    float y = d * rsqrtf(var + 1e-5f) * gamma[tid] + beta[tid];

    merged[tid] = qe_s[tid];
    merged[D_DIM + tid] = y;
    __syncthreads();

    for (int c = wid; c < C_CLS; c += 8) {
        const float* wr = Wc + c * 2 * D_DIM;
        float p = 0.f;
#pragma unroll
        for (int i = 0; i < 16; i++) p += merged[lane + 32 * i] * wr[lane + 32 * i];
        for (int o = 16; o > 0; o >>= 1) p += __shfl_xor_sync(0xffffffffu, p, o);
        if (lane == 0) out[b * C_CLS + c] = p + bc[c];
    }
}

// ---------------- launch ------------------------------------------------------
extern "C" void kernel_launch(void* const* d_in, const int* in_sizes, int n_in,
                              void* d_out, int out_size) {
    const float* query = (const float*)d_in[0];
    const float* mk    = (const float*)d_in[1];
    const float* Wd    = (const float*)d_in[2];
    const float* bd    = (const float*)d_in[3];
    const float* gamma = (const float*)d_in[4];
    const float* beta  = (const float*)d_in[5];
    const float* Wc    = (const float*)d_in[6];
    const float* bc    = (const float*)d_in[7];
    float* out = (float*)d_out;

    cudaFuncSetAttribute(gemm_kernel, cudaFuncAttributeMaxDynamicSharedMemorySize, SM_TOT);

    prep_kernel<<<B_Q, 256>>>(query, Wd, bd);
    gemm_kernel<<<NTILES, 256, SM_TOT>>>(mk);
    thresh_kernel<<<B_Q, 256>>>();
    select_kernel<<<B_Q, 256>>>(mk);
    tail_kernel<<<B_Q, 256>>>(mk, Wc, bc, gamma, beta, out);
}

// round 7
// speedup vs baseline: 4.2644x; 1.3648x over previous
#include <cuda_runtime.h>
#include <cuda_bf16.h>
#include <cstdint>

#define B_Q    256
#define D_DIM  256
#define NMEM   500000
#define K_NN   64
#define C_CLS  50
#define NTILES 3907          // ceil(500000/128)
#define CT_CAP 1024
#define CE_CAP 2048
#define MARGIN 16            // key-ULP safety margin (~13 sigma of bf16 MMA+key error)

// ---------------- device scratch (no allocation allowed) ---------------------
__device__ unsigned short g_keys[(size_t)B_Q * NMEM];     // 256 MB monotone bf16 keys
__device__ unsigned short g_tmax[(size_t)B_Q * NTILES];   // per (row, tile) max key
__device__ int   g_ctiles[B_Q * CT_CAP];
__device__ int   g_ctilecnt[B_Q];
__device__ int   g_tau[B_Q];
__device__ float g_qe[B_Q * D_DIM];
__device__ float g_qt[B_Q * D_DIM];
__device__ int   g_topk[B_Q * K_NN];
__device__ __nv_bfloat162 g_A[B_Q * D_DIM / 2];           // qe in bf16, row-major

// ---------------- helpers ----------------------------------------------------
__device__ __forceinline__ uint32_t smem_u32(const void* p) {
    uint32_t a;
    asm("{ .reg .u64 t; cvta.to.shared.u64 t, %1; cvt.u32.u64 %0, t; }" : "=r"(a) : "l"(p));
    return a;
}
__device__ __forceinline__ void ldsm4(uint32_t& r0, uint32_t& r1, uint32_t& r2,
                                      uint32_t& r3, uint32_t addr) {
    asm volatile("ldmatrix.sync.aligned.m8n8.x4.shared.b16 {%0,%1,%2,%3}, [%4];"
                 : "=r"(r0), "=r"(r1), "=r"(r2), "=r"(r3) : "r"(addr));
}
__device__ __forceinline__ void mma16816(float* c, const uint32_t* a, const uint32_t* b) {
    asm volatile(
        "mma.sync.aligned.m16n8k16.row.col.f32.bf16.bf16.f32 "
        "{%0,%1,%2,%3}, {%4,%5,%6,%7}, {%8,%9}, {%0,%1,%2,%3};"
        : "+f"(c[0]), "+f"(c[1]), "+f"(c[2]), "+f"(c[3])
        : "r"(a[0]), "r"(a[1]), "r"(a[2]), "r"(a[3]), "r"(b[0]), "r"(b[1]));
}
__device__ __forceinline__ unsigned short tokey(float v) {
    unsigned short u = __bfloat16_as_ushort(__float2bfloat16(v));
    return (u & 0x8000) ? (unsigned short)(~u) : (unsigned short)(u | 0x8000);
}
__device__ __forceinline__ uint32_t fkey32(float f) {
    uint32_t u = __float_as_uint(f);
    return (u & 0x80000000u) ? ~u : (u | 0x80000000u);
}

// ---------------- kernel 1: qe, qt, bf16 A ------------------------------------
__global__ void prep_kernel(const float* __restrict__ query,
                            const float* __restrict__ Wd,
                            const float* __restrict__ bd) {
    int b = blockIdx.x, tid = threadIdx.x;
    __shared__ float qs[D_DIM];
    float q = fmaxf(query[b * D_DIM + tid], 0.f);
    qs[tid] = q;
    g_qe[b * D_DIM + tid] = q;
    __syncthreads();

    if (tid < 128)
        g_A[b * 128 + tid] = __float22bfloat162_rn(make_float2(qs[2 * tid], qs[2 * tid + 1]));

    const float4* w4 = (const float4*)(Wd + tid * D_DIM);
    const float4* q4 = (const float4*)qs;
    float acc = bd[tid];
#pragma unroll 8
    for (int i = 0; i < D_DIM / 4; i++) {
        float4 a = q4[i], w = w4[i];
        acc += a.x * w.x + a.y * w.y + a.z * w.z + a.w * w.w;
    }
    g_qt[b * D_DIM + tid] = fmaxf(acc, 0.f);
}

// ---------------- kernel 2: bf16 HMMA GEMM + key epilogue ---------------------
#define SM_INV  0
#define SM_AOFF 512
#define APITCH  528
#define SM_BOFF 136192
#define SM_TOT  203776
#define STPITCH 272   // stage: 256 rows x 272 B (136 u16)

__global__ void __launch_bounds__(256, 1)
gemm_kernel(const float* __restrict__ mk) {
    extern __shared__ char smem[];
    const uint32_t sb = smem_u32(smem);
    float* invn_s = (float*)(smem + SM_INV);
    const int tid = threadIdx.x;
    const int wid = tid >> 5, lane = tid & 31;
    const int bx = blockIdx.x;
    const int n0 = bx * 128;

    // ---- A: g_A (bf16 row-major, L2-resident) -> smem pitch 528 ----
    {
        const uint4* src = (const uint4*)g_A;
#pragma unroll
        for (int i = 0; i < 32; i++) {
            int row = i * 8 + wid;
            *(uint4*)(smem + SM_AOFF + row * APITCH + lane * 16) = src[row * 32 + lane];
        }
    }

    // ---- B: fp32 global -> bf16 smem pitch 528, fused row sumsq ----
    {
#pragma unroll
        for (int i = 0; i < 16; i++) {
            int r = i * 8 + wid;
            int n = n0 + r;
            float4 v0 = make_float4(0.f, 0.f, 0.f, 0.f), v1 = v0;
            if (n < NMEM) {
                const float* rp = mk + (size_t)n * D_DIM + lane * 8;
                v0 = *(const float4*)rp;
                v1 = *(const float4*)(rp + 4);
            }
            float s = v0.x * v0.x + v0.y * v0.y + v0.z * v0.z + v0.w * v0.w
                    + v1.x * v1.x + v1.y * v1.y + v1.z * v1.z + v1.w * v1.w;
#pragma unroll
            for (int o = 16; o > 0; o >>= 1) s += __shfl_xor_sync(0xffffffffu, s, o);
            if (lane == 0) invn_s[r] = s;
            __nv_bfloat162 p0 = __float22bfloat162_rn(make_float2(v0.x, v0.y));
            __nv_bfloat162 p1 = __float22bfloat162_rn(make_float2(v0.z, v0.w));
            __nv_bfloat162 p2 = __float22bfloat162_rn(make_float2(v1.x, v1.y));
            __nv_bfloat162 p3 = __float22bfloat162_rn(make_float2(v1.z, v1.w));
            *(uint4*)(smem + SM_BOFF + r * APITCH + lane * 16) =
                make_uint4(*(uint32_t*)&p0, *(uint32_t*)&p1, *(uint32_t*)&p2, *(uint32_t*)&p3);
        }
    }
    __syncthreads();
    if (tid < 128) invn_s[tid] = 1.f / fmaxf(sqrtf(invn_s[tid]), 1e-8f);
    __syncthreads();

    // ---- MMA mainloop: warp grid 4(M) x 2(N); 64x64 per warp ----
    const int wm = wid >> 1, wn = wid & 1;
    const int m_base = wm * 64, n_base = wn * 64;

    float acc[4][8][4];
#pragma unroll
    for (int mi = 0; mi < 4; mi++)
#pragma unroll
        for (int nj = 0; nj < 8; nj++)
#pragma unroll
            for (int r = 0; r < 4; r++) acc[mi][nj][r] = 0.f;

    const int a_row = ((lane >> 3) & 1) * 8 + (lane & 7);
    const int a_col = (lane >> 4) * 8;
    const int b_row = (lane >> 4) * 8 + (lane & 7);
    const int b_col = ((lane >> 3) & 1) * 8;

    uint32_t pa[4], pb[4];
#pragma unroll
    for (int mi = 0; mi < 4; mi++)
        pa[mi] = sb + SM_AOFF + (m_base + mi * 16 + a_row) * APITCH + a_col * 2;
#pragma unroll
    for (int nb = 0; nb < 4; nb++)
        pb[nb] = sb + SM_BOFF + (n_base + nb * 16 + b_row) * APITCH + b_col * 2;

#pragma unroll 2
    for (int ks = 0; ks < 16; ks++) {
        const int koff = ks * 32;
        uint32_t af[4][4], bf[4][4];
#pragma unroll
        for (int mi = 0; mi < 4; mi++)
            ldsm4(af[mi][0], af[mi][1], af[mi][2], af[mi][3], pa[mi] + koff);
#pragma unroll
        for (int nb = 0; nb < 4; nb++)
            ldsm4(bf[nb][0], bf[nb][1], bf[nb][2], bf[nb][3], pb[nb] + koff);
#pragma unroll
        for (int mi = 0; mi < 4; mi++)
#pragma unroll
            for (int nj = 0; nj < 8; nj++)
                mma16816(acc[mi][nj], af[mi], &bf[nj >> 1][(nj & 1) * 2]);
    }

    __syncthreads();

    // ---- stage keys in smem (reuse A region) ----
    {
        char* stage = smem + SM_AOFF;
#pragma unroll
        for (int mi = 0; mi < 4; mi++) {
#pragma unroll
            for (int nj = 0; nj < 8; nj++) {
                int nl = n_base + nj * 8 + (lane & 3) * 2;
                int ng = n0 + nl;
                float i0 = invn_s[nl], i1 = invn_s[nl + 1];
                int m0 = m_base + mi * 16 + (lane >> 2);
#pragma unroll
                for (int g = 0; g < 2; g++) {
                    int m = m0 + g * 8;
                    unsigned short k0 = 0, k1 = 0;
                    if (ng < NMEM)     k0 = tokey(acc[mi][nj][2 * g] * i0);
                    if (ng + 1 < NMEM) k1 = tokey(acc[mi][nj][2 * g + 1] * i1);
                    *(uint32_t*)(stage + m * STPITCH + nl * 2) =
                        (uint32_t)k0 | ((uint32_t)k1 << 16);
                }
            }
        }
    }
    __syncthreads();

    // ---- coalesced global write + per-(row, tile) max ----
    {
        const char* stage = smem + SM_AOFF;
        const int part = tid & 1;
#pragma unroll
        for (int half = 0; half < 2; half++) {
            const int m = (tid >> 1) + half * 128;
            const unsigned short* srow = (const unsigned short*)(stage + m * STPITCH);
            unsigned short* drow = g_keys + (size_t)m * NMEM + n0;
            uint32_t kmax = 0;
#pragma unroll
            for (int i = 0; i < 8; i++) {
                int c = (i * 2 + part) * 8;
                uint4 v = *(const uint4*)(srow + c);
                const unsigned short* u = (const unsigned short*)&v;
#pragma unroll
                for (int j = 0; j < 8; j++) kmax = max(kmax, (uint32_t)u[j]);
                if (n0 + c + 8 <= NMEM) *(uint4*)(drow + c) = v;
            }
            uint32_t other = __shfl_xor_sync(0xffffffffu, kmax, 1);
            kmax = max(kmax, other);
            if (part == 0) g_tmax[(size_t)m * NTILES + bx] = (unsigned short)kmax;
        }
    }
}

// ---------------- kernel 3: exact 64th tile-max (16-bit) + candidate tiles ----
__global__ void thresh_kernel() {
    const int row = blockIdx.x, tid = threadIdx.x;
    __shared__ uint32_t hist[256];
    __shared__ int s_b, s_r, s_tau, s_cnt;

    const unsigned short* tm = g_tmax + (size_t)row * NTILES;

    // pass 1: high byte
    if (tid < 256) hist[tid] = 0;
    if (tid == 0) s_cnt = 0;
    __syncthreads();
    for (int i = tid; i < NTILES; i += 256)
        atomicAdd(&hist[tm[i] >> 8], 1u);
    __syncthreads();
    if (tid == 0) {
        int cum = 0, b = 255;
        for (; b >= 0; b--) {
            if (cum + (int)hist[b] >= K_NN) break;
            cum += (int)hist[b];
        }
        s_b = b;
        s_r = K_NN - cum;   // need r-th largest low-byte within bin b
    }
    __syncthreads();
    const int b = s_b, r = s_r;

    // pass 2: low byte within high-byte bin b
    if (tid < 256) hist[tid] = 0;
    __syncthreads();
    for (int i = tid; i < NTILES; i += 256) {
        unsigned short v = tm[i];
        if ((v >> 8) == b) atomicAdd(&hist[v & 255], 1u);
    }
    __syncthreads();
    if (tid == 0) {
        int cum = 0, lb = 255;
        for (; lb >= 0; lb--) {
            cum += (int)hist[lb];
            if (cum >= r) break;
        }
        int v64k = (b << 8) | lb;
        int tau = v64k - MARGIN;
        if (tau < 0) tau = 0;
        s_tau = tau;
        g_tau[row] = tau;
    }
    __syncthreads();
    const int tau = s_tau;

    for (int i = tid; i < NTILES; i += 256) {
        if ((int)tm[i] >= tau) {
            int p = atomicAdd(&s_cnt, 1);
            if (p < CT_CAP) g_ctiles[row * CT_CAP + p] = i;
        }
    }
    __syncthreads();
    if (tid == 0) g_ctilecnt[row] = min(s_cnt, CT_CAP);
}

// ---------------- kernel 4: gather + exact rescore + bitonic top-64 -----------
__global__ void select_kernel(const float* __restrict__ mk) {
    const int row = blockIdx.x, tid = threadIdx.x;
    const int wid = tid >> 5, lane = tid & 31;
    __shared__ int   cidx[CE_CAP];
    __shared__ unsigned long long arr[CE_CAP];
    __shared__ float qe_s[D_DIM];
    __shared__ int   s_cnt;

    if (tid == 0) s_cnt = 0;
    qe_s[tid] = g_qe[row * D_DIM + tid];
    __syncthreads();

    const int tau = g_tau[row];
    const int tcnt = g_ctilecnt[row];
    const unsigned short* keys = g_keys + (size_t)row * NMEM;

    for (int p = tid; p < tcnt * 128; p += 256) {
        int t = g_ctiles[row * CT_CAP + (p >> 7)];
        int n = t * 128 + (p & 127);
        if (n < NMEM && (int)keys[n] >= tau) {
            int q = atomicAdd(&s_cnt, 1);
            if (q < CE_CAP) cidx[q] = n;
        }
    }
    __syncthreads();
    const int nc = min(s_cnt, CE_CAP);

    // exact fp32 cosine rescore (query norm: positive per-row constant, omitted)
    for (int c = wid; c < nc; c += 8) {
        const float* rr = mk + (size_t)cidx[c] * D_DIM;
        float d = 0.f, s = 0.f;
#pragma unroll
        for (int i = 0; i < 8; i++) {
            float x = rr[lane + 32 * i];
            d += qe_s[lane + 32 * i] * x;
            s += x * x;
        }
#pragma unroll
        for (int o = 16; o > 0; o >>= 1) {
            d += __shfl_xor_sync(0xffffffffu, d, o);
            s += __shfl_xor_sync(0xffffffffu, s, o);
        }
        if (lane == 0) {
            float v = d / fmaxf(sqrtf(s), 1e-8f);
            arr[c] = ((unsigned long long)fkey32(v) << 32) | (uint32_t)(~cidx[c]);
        }
    }
    __syncthreads();

    // pad to pow2 and bitonic sort descending
    int NS = 128;
    while (NS < nc) NS <<= 1;
    for (int i = nc + tid; i < NS; i += 256) arr[i] = 0ull;
    __syncthreads();

    for (int k = 2; k <= NS; k <<= 1) {
        for (int j = k >> 1; j > 0; j >>= 1) {
            for (int t = tid; t < NS; t += 256) {
                int ixj = t ^ j;
                if (ixj > t) {
                    bool desc = ((t & k) == 0);
                    unsigned long long a = arr[t], bb = arr[ixj];
                    if ((a < bb) == desc) { arr[t] = bb; arr[ixj] = a; }
                }
            }
            __syncthreads();
        }
    }

    if (tid < K_NN)
        g_topk[row * K_NN + tid] = (int)(~(uint32_t)arr[tid]);
}

// ---------------- kernel 5: attention + layernorm + classifier ----------------
__global__ void tail_kernel(const float* __restrict__ mk,
                            const float* __restrict__ Wc,
                            const float* __restrict__ bc,
                            const float* __restrict__ gamma,
                            const float* __restrict__ beta,
                            float* __restrict__ out) {
    const int b = blockIdx.x, tid = threadIdx.x;
    const int wid = tid >> 5, lane = tid & 31;
    __shared__ float qe_s[D_DIM], qt_s[D_DIM], sc[K_NN], wgt[K_NN];
    __shared__ int idxs[K_NN];
    __shared__ float merged[2 * D_DIM];
    __shared__ float red[256];

    qe_s[tid] = g_qe[b * D_DIM + tid];
    qt_s[tid] = g_qt[b * D_DIM + tid];
    if (tid < K_NN) idxs[tid] = g_topk[b * K_NN + tid];
    __syncthreads();

    for (int j = wid; j < K_NN; j += 8) {
        const float* r = mk + (size_t)idxs[j] * D_DIM;
        float p = 0.f;
#pragma unroll
        for (int i = 0; i < 8; i++) p += qt_s[lane + 32 * i] * r[lane + 32 * i];
        for (int o = 16; o > 0; o >>= 1) p += __shfl_xor_sync(0xffffffffu, p, o);
        if (lane == 0) sc[j] = p;
    }
    __syncthreads();

    if (wid == 0) {
        float v0 = sc[lane], v1 = sc[lane + 32];
        float mx = fmaxf(v0, v1);
        for (int o = 16; o > 0; o >>= 1) mx = fmaxf(mx, __shfl_xor_sync(0xffffffffu, mx, o));
        float e0 = expf(v0 - mx), e1 = expf(v1 - mx);
        float s = e0 + e1;
        for (int o = 16; o > 0; o >>= 1) s += __shfl_xor_sync(0xffffffffu, s, o);
        float is = 1.f / s;
        wgt[lane] = e0 * is;
        wgt[lane + 32] = e1 * is;
    }
    __syncthreads();

    float acc = 0.f;
    for (int j = 0; j < K_NN; j++)
        acc += wgt[j] * mk[(size_t)idxs[j] * D_DIM + tid];
    float r = acc + qe_s[tid];

    red[tid] = r;
    __syncthreads();
    for (int s = 128; s > 0; s >>= 1) {
        if (tid < s) red[tid] += red[tid + s];
        __syncthreads();
    }
    float mu = red[0] / (float)D_DIM;
    __syncthreads();
    float d = r - mu;
    red[tid] = d * d;
    __syncthreads();
    for (int s = 128; s > 0; s >>= 1) {
        if (tid < s) red[tid] += red[tid + s];
        __syncthreads();
    }
    float var = red[0] / (float)D_DIM;
    float y = d * rsqrtf(var + 1e-5f) * gamma[tid] + beta[tid];

    merged[tid] = qe_s[tid];
    merged[D_DIM + tid] = y;
    __syncthreads();

    for (int c = wid; c < C_CLS; c += 8) {
        const float* wr = Wc + c * 2 * D_DIM;
        float p = 0.f;
#pragma unroll
        for (int i = 0; i < 16; i++) p += merged[lane + 32 * i] * wr[lane + 32 * i];
        for (int o = 16; o > 0; o >>= 1) p += __shfl_xor_sync(0xffffffffu, p, o);
        if (lane == 0) out[b * C_CLS + c] = p + bc[c];
    }
}

// ---------------- launch ------------------------------------------------------
extern "C" void kernel_launch(void* const* d_in, const int* in_sizes, int n_in,
                              void* d_out, int out_size) {
    const float* query = (const float*)d_in[0];
    const float* mk    = (const float*)d_in[1];
    const float* Wd    = (const float*)d_in[2];
    const float* bd    = (const float*)d_in[3];
    const float* gamma = (const float*)d_in[4];
    const float* beta  = (const float*)d_in[5];
    const float* Wc    = (const float*)d_in[6];
    const float* bc    = (const float*)d_in[7];
    float* out = (float*)d_out;

    cudaFuncSetAttribute(gemm_kernel, cudaFuncAttributeMaxDynamicSharedMemorySize, SM_TOT);

    prep_kernel<<<B_Q, 256>>>(query, Wd, bd);
    gemm_kernel<<<NTILES, 256, SM_TOT>>>(mk);
    thresh_kernel<<<B_Q, 256>>>();
    select_kernel<<<B_Q, 256>>>(mk);
    tail_kernel<<<B_Q, 256>>>(mk, Wc, bc, gamma, beta, out);
}

// round 12
// speedup vs baseline: 4.7187x; 1.1065x over previous
#include <cuda_runtime.h>
#include <cuda_bf16.h>
#include <cstdint>

#define B_Q    256
#define D_DIM  256
#define NMEM   500000
#define K_NN   64
#define C_CLS  50
#define NTILES 3907          // ceil(500000/128)
#define CT_CAP 1024
#define CE_CAP 2048
#define MARGIN 16            // key-ULP safety margin (~13 sigma of bf16 MMA+key error)

// ---------------- device scratch (no allocation allowed) ---------------------
__device__ unsigned short g_keys[(size_t)B_Q * NMEM];     // 256 MB monotone bf16 keys
__device__ unsigned short g_tmax[(size_t)B_Q * NTILES];   // per (row, tile) max key
__device__ int   g_tau[B_Q];
__device__ float g_qe[B_Q * D_DIM];
__device__ float g_qt[B_Q * D_DIM];
__device__ int   g_topk[B_Q * K_NN];
__device__ __nv_bfloat162 g_A[B_Q * D_DIM / 2];           // qe in bf16, row-major

// ---------------- helpers ----------------------------------------------------
__device__ __forceinline__ uint32_t smem_u32(const void* p) {
    uint32_t a;
    asm("{ .reg .u64 t; cvta.to.shared.u64 t, %1; cvt.u32.u64 %0, t; }" : "=r"(a) : "l"(p));
    return a;
}
__device__ __forceinline__ void ldsm4(uint32_t& r0, uint32_t& r1, uint32_t& r2,
                                      uint32_t& r3, uint32_t addr) {
    asm volatile("ldmatrix.sync.aligned.m8n8.x4.shared.b16 {%0,%1,%2,%3}, [%4];"
                 : "=r"(r0), "=r"(r1), "=r"(r2), "=r"(r3) : "r"(addr));
}
__device__ __forceinline__ void mma16816(float* c, const uint32_t* a, const uint32_t* b) {
    asm volatile(
        "mma.sync.aligned.m16n8k16.row.col.f32.bf16.bf16.f32 "
        "{%0,%1,%2,%3}, {%4,%5,%6,%7}, {%8,%9}, {%0,%1,%2,%3};"
        : "+f"(c[0]), "+f"(c[1]), "+f"(c[2]), "+f"(c[3])
        : "r"(a[0]), "r"(a[1]), "r"(a[2]), "r"(a[3]), "r"(b[0]), "r"(b[1]));
}
__device__ __forceinline__ unsigned short tokey(float v) {
    unsigned short u = __bfloat16_as_ushort(__float2bfloat16(v));
    return (u & 0x8000) ? (unsigned short)(~u) : (unsigned short)(u | 0x8000);
}
__device__ __forceinline__ uint32_t fkey32(float f) {
    uint32_t u = __float_as_uint(f);
    return (u & 0x80000000u) ? ~u : (u | 0x80000000u);
}

// ---------------- kernel 1: qe, qt, bf16 A ------------------------------------
__global__ void prep_kernel(const float* __restrict__ query,
                            const float* __restrict__ Wd,
                            const float* __restrict__ bd) {
    int b = blockIdx.x, tid = threadIdx.x;
    __shared__ float qs[D_DIM];
    float q = fmaxf(query[b * D_DIM + tid], 0.f);
    qs[tid] = q;
    g_qe[b * D_DIM + tid] = q;
    __syncthreads();

    if (tid < 128)
        g_A[b * 128 + tid] = __float22bfloat162_rn(make_float2(qs[2 * tid], qs[2 * tid + 1]));

    const float4* w4 = (const float4*)(Wd + tid * D_DIM);
    const float4* q4 = (const float4*)qs;
    float acc = bd[tid];
#pragma unroll 8
    for (int i = 0; i < D_DIM / 4; i++) {
        float4 a = q4[i], w = w4[i];
        acc += a.x * w.x + a.y * w.y + a.z * w.z + a.w * w.w;
    }
    g_qt[b * D_DIM + tid] = fmaxf(acc, 0.f);
}

// ---------------- kernel 2: bf16 HMMA GEMM, k-chunk pipelined -----------------
#define SM_INV  0
#define SM_AOFF 512
#define APITCH  528
#define SM_B0   135680
#define SM_B1   170496
#define BPITCH  272
#define SM_TOT  205312
#define STPITCH 272   // key stage: 256 rows x 272 B

__global__ void __launch_bounds__(256, 1)
gemm_kernel(const float* __restrict__ mk) {
    extern __shared__ char smem[];
    const uint32_t sb = smem_u32(smem);
    float* invn_s = (float*)(smem + SM_INV);
    const int tid = threadIdx.x;
    const int wid = tid >> 5, lane = tid & 31;
    const int bx = blockIdx.x;
    const int n0 = bx * 128;

    // ---- A: g_A (bf16 row-major, L2-resident) -> smem pitch 528 ----
    {
        const uint4* src = (const uint4*)g_A;
#pragma unroll
        for (int i = 0; i < 32; i++) {
            int row = i * 8 + wid;
            *(uint4*)(smem + SM_AOFF + row * APITCH + lane * 16) = src[row * 32 + lane];
        }
    }

    // ---- B chunk0 (k 0..127): fp32 -> bf16, fused row sumsq ----
    {
#pragma unroll
        for (int j = 0; j < 16; j++) {
            int r = wid * 16 + j;
            int n = n0 + r;
            const float4* src = (const float4*)(mk + (size_t)(n < NMEM ? n : 0) * D_DIM) + lane;
            float4 v = *src;
            if (n >= NMEM) v = make_float4(0.f, 0.f, 0.f, 0.f);
            float s = v.x * v.x + v.y * v.y + v.z * v.z + v.w * v.w;
#pragma unroll
            for (int o = 16; o > 0; o >>= 1) s += __shfl_xor_sync(0xffffffffu, s, o);
            if (lane == 0) invn_s[r] = s;
            __nv_bfloat162 p0 = __float22bfloat162_rn(make_float2(v.x, v.y));
            __nv_bfloat162 p1 = __float22bfloat162_rn(make_float2(v.z, v.w));
            *(uint2*)(smem + SM_B0 + r * BPITCH + lane * 8) =
                make_uint2(*(uint32_t*)&p0, *(uint32_t*)&p1);
        }
    }
    __syncthreads();

    // ---- MMA setup: warp grid 4(M) x 2(N); 64x64 per warp ----
    const int wm = wid >> 1, wn = wid & 1;
    const int m_base = wm * 64, n_base = wn * 64;

    float acc[4][8][4];
#pragma unroll
    for (int mi = 0; mi < 4; mi++)
#pragma unroll
        for (int nj = 0; nj < 8; nj++)
#pragma unroll
            for (int r = 0; r < 4; r++) acc[mi][nj][r] = 0.f;

    const int a_row = ((lane >> 3) & 1) * 8 + (lane & 7);
    const int a_col = (lane >> 4) * 8;
    const int b_row = (lane >> 4) * 8 + (lane & 7);
    const int b_col = ((lane >> 3) & 1) * 8;

    uint32_t pa[4], pb0[4], pb1[4];
#pragma unroll
    for (int mi = 0; mi < 4; mi++)
        pa[mi] = sb + SM_AOFF + (m_base + mi * 16 + a_row) * APITCH + a_col * 2;
#pragma unroll
    for (int nb = 0; nb < 4; nb++) {
        pb0[nb] = sb + SM_B0 + (n_base + nb * 16 + b_row) * BPITCH + b_col * 2;
        pb1[nb] = sb + SM_B1 + (n_base + nb * 16 + b_row) * BPITCH + b_col * 2;
    }

    auto mma_step = [&](const uint32_t* pb, int akoff, int bkoff) {
        uint32_t af[4][4], bf[4][4];
#pragma unroll
        for (int mi = 0; mi < 4; mi++)
            ldsm4(af[mi][0], af[mi][1], af[mi][2], af[mi][3], pa[mi] + akoff);
#pragma unroll
        for (int nb = 0; nb < 4; nb++)
            ldsm4(bf[nb][0], bf[nb][1], bf[nb][2], bf[nb][3], pb[nb] + bkoff);
#pragma unroll
        for (int mi = 0; mi < 4; mi++)
#pragma unroll
            for (int nj = 0; nj < 8; nj++)
                mma16816(acc[mi][nj], af[mi], &bf[nj >> 1][(nj & 1) * 2]);
    };

    // ---- chunk0 MMA with chunk1 prefetch (two 8-row sub-batches) ----
    float4 breg[8];
#pragma unroll
    for (int j = 0; j < 8; j++) {                       // prefetch rows wid*16+0..7 of chunk1
        int n = n0 + wid * 16 + j;
        breg[j] = *((const float4*)(mk + (size_t)(n < NMEM ? n : 0) * D_DIM + 128) + lane);
    }
#pragma unroll
    for (int ks = 0; ks < 4; ks++) mma_step(pb0, ks * 32, ks * 32);
#pragma unroll
    for (int j = 0; j < 8; j++) {                       // store sub-batch 0
        int r = wid * 16 + j;
        int n = n0 + r;
        float4 v = breg[j];
        if (n >= NMEM) v = make_float4(0.f, 0.f, 0.f, 0.f);
        float s = v.x * v.x + v.y * v.y + v.z * v.z + v.w * v.w;
#pragma unroll
        for (int o = 16; o > 0; o >>= 1) s += __shfl_xor_sync(0xffffffffu, s, o);
        if (lane == 0) invn_s[r] += s;
        __nv_bfloat162 p0 = __float22bfloat162_rn(make_float2(v.x, v.y));
        __nv_bfloat162 p1 = __float22bfloat162_rn(make_float2(v.z, v.w));
        *(uint2*)(smem + SM_B1 + r * BPITCH + lane * 8) =
            make_uint2(*(uint32_t*)&p0, *(uint32_t*)&p1);
    }
#pragma unroll
    for (int j = 0; j < 8; j++) {                       // prefetch rows wid*16+8..15
        int n = n0 + wid * 16 + 8 + j;
        breg[j] = *((const float4*)(mk + (size_t)(n < NMEM ? n : 0) * D_DIM + 128) + lane);
    }
#pragma unroll
    for (int ks = 4; ks < 8; ks++) mma_step(pb0, ks * 32, ks * 32);
#pragma unroll
    for (int j = 0; j < 8; j++) {                       // store sub-batch 1
        int r = wid * 16 + 8 + j;
        int n = n0 + r;
        float4 v = breg[j];
        if (n >= NMEM) v = make_float4(0.f, 0.f, 0.f, 0.f);
        float s = v.x * v.x + v.y * v.y + v.z * v.z + v.w * v.w;
#pragma unroll
        for (int o = 16; o > 0; o >>= 1) s += __shfl_xor_sync(0xffffffffu, s, o);
        if (lane == 0) invn_s[r] += s;
        __nv_bfloat162 p0 = __float22bfloat162_rn(make_float2(v.x, v.y));
        __nv_bfloat162 p1 = __float22bfloat162_rn(make_float2(v.z, v.w));
        *(uint2*)(smem + SM_B1 + r * BPITCH + lane * 8) =
            make_uint2(*(uint32_t*)&p0, *(uint32_t*)&p1);
    }
    __syncthreads();

    if (tid < 128) invn_s[tid] = 1.f / fmaxf(sqrtf(invn_s[tid]), 1e-8f);

    // ---- chunk1 MMA ----
#pragma unroll
    for (int ks = 0; ks < 8; ks++) mma_step(pb1, (8 + ks) * 32, ks * 32);

    __syncthreads();

    // ---- stage keys in smem (reuse A region) ----
    {
        char* stage = smem + SM_AOFF;
#pragma unroll
        for (int mi = 0; mi < 4; mi++) {
#pragma unroll
            for (int nj = 0; nj < 8; nj++) {
                int nl = n_base + nj * 8 + (lane & 3) * 2;
                int ng = n0 + nl;
                float i0 = invn_s[nl], i1 = invn_s[nl + 1];
                int m0 = m_base + mi * 16 + (lane >> 2);
#pragma unroll
                for (int g = 0; g < 2; g++) {
                    int m = m0 + g * 8;
                    unsigned short k0 = 0, k1 = 0;
                    if (ng < NMEM)     k0 = tokey(acc[mi][nj][2 * g] * i0);
                    if (ng + 1 < NMEM) k1 = tokey(acc[mi][nj][2 * g + 1] * i1);
                    *(uint32_t*)(stage + m * STPITCH + nl * 2) =
                        (uint32_t)k0 | ((uint32_t)k1 << 16);
                }
            }
        }
    }
    __syncthreads();

    // ---- coalesced global write + per-(row, tile) max ----
    {
        const char* stage = smem + SM_AOFF;
        const int part = tid & 1;
#pragma unroll
        for (int half = 0; half < 2; half++) {
            const int m = (tid >> 1) + half * 128;
            const unsigned short* srow = (const unsigned short*)(stage + m * STPITCH);
            unsigned short* drow = g_keys + (size_t)m * NMEM + n0;
            uint32_t kmax = 0;
#pragma unroll
            for (int i = 0; i < 8; i++) {
                int c = (i * 2 + part) * 8;
                uint4 v = *(const uint4*)(srow + c);
                const unsigned short* u = (const unsigned short*)&v;
#pragma unroll
                for (int j = 0; j < 8; j++) kmax = max(kmax, (uint32_t)u[j]);
                if (n0 + c + 8 <= NMEM) *(uint4*)(drow + c) = v;
            }
            uint32_t other = __shfl_xor_sync(0xffffffffu, kmax, 1);
            kmax = max(kmax, other);
            if (part == 0) g_tmax[(size_t)m * NTILES + bx] = (unsigned short)kmax;
        }
    }
}

// ---------------- kernel 3: fused threshold + gather + rescore + top-64 -------
__global__ void __launch_bounds__(512)
select_kernel(const float* __restrict__ mk) {
    const int row = blockIdx.x, tid = threadIdx.x;
    const int wid = tid >> 5, lane = tid & 31;
    __shared__ uint32_t hist[256];
    __shared__ int s_b, s_r, s_tau, s_tcnt, s_cnt;
    __shared__ int ctile[CT_CAP];
    __shared__ float qe_s[D_DIM];
    __shared__ int cidx[CE_CAP];
    __shared__ unsigned long long arr[CE_CAP];

    const unsigned short* tm = g_tmax + (size_t)row * NTILES;

    if (tid < 256) { hist[tid] = 0; qe_s[tid] = g_qe[row * D_DIM + tid]; }
    if (tid == 0) { s_cnt = 0; s_tcnt = 0; }
    __syncthreads();

    // exact 64th-largest tile-max: pass 1 (high byte)
    for (int i = tid; i < NTILES; i += 512) atomicAdd(&hist[tm[i] >> 8], 1u);
    __syncthreads();
    if (tid == 0) {
        int cum = 0, b = 255;
        for (; b >= 0; b--) {
            if (cum + (int)hist[b] >= K_NN) break;
            cum += (int)hist[b];
        }
        s_b = b; s_r = K_NN - cum;
    }
    __syncthreads();
    const int bb = s_b, rr = s_r;
    if (tid < 256) hist[tid] = 0;
    __syncthreads();
    // pass 2 (low byte within bin)
    for (int i = tid; i < NTILES; i += 512) {
        unsigned short v = tm[i];
        if ((v >> 8) == bb) atomicAdd(&hist[v & 255], 1u);
    }
    __syncthreads();
    if (tid == 0) {
        int cum = 0, lb = 255;
        for (; lb >= 0; lb--) {
            cum += (int)hist[lb];
            if (cum >= rr) break;
        }
        int tau = ((bb << 8) | lb) - MARGIN;
        if (tau < 0) tau = 0;
        s_tau = tau;
    }
    __syncthreads();
    const int tau = s_tau;

    // candidate tiles
    for (int i = tid; i < NTILES; i += 512) {
        if ((int)tm[i] >= tau) {
            int p = atomicAdd(&s_tcnt, 1);
            if (p < CT_CAP) ctile[p] = i;
        }
    }
    __syncthreads();
    const int tcnt = min(s_tcnt, CT_CAP);
    const unsigned short* keys = g_keys + (size_t)row * NMEM;

    // candidate elements
    for (int p = tid; p < tcnt * 128; p += 512) {
        int t = ctile[p >> 7];
        int n = t * 128 + (p & 127);
        if (n < NMEM && (int)keys[n] >= tau) {
            int q = atomicAdd(&s_cnt, 1);
            if (q < CE_CAP) cidx[q] = n;
        }
    }
    __syncthreads();
    const int nc = min(s_cnt, CE_CAP);

    // exact fp32 rescore, 16 warps, 2 rows in flight per warp iteration
    for (int c0 = wid; c0 < nc; c0 += 32) {
        int c1 = c0 + 16;
        bool has1 = (c1 < nc);
        const float* r0 = mk + (size_t)cidx[c0] * D_DIM;
        const float* r1 = mk + (size_t)cidx[has1 ? c1 : c0] * D_DIM;
        float d0 = 0.f, s0 = 0.f, d1 = 0.f, s1 = 0.f;
#pragma unroll
        for (int i = 0; i < 8; i++) {
            float qv = qe_s[lane + 32 * i];
            float x0 = r0[lane + 32 * i];
            float x1 = r1[lane + 32 * i];
            d0 += qv * x0; s0 += x0 * x0;
            d1 += qv * x1; s1 += x1 * x1;
        }
#pragma unroll
        for (int o = 16; o > 0; o >>= 1) {
            d0 += __shfl_xor_sync(0xffffffffu, d0, o);
            s0 += __shfl_xor_sync(0xffffffffu, s0, o);
            d1 += __shfl_xor_sync(0xffffffffu, d1, o);
            s1 += __shfl_xor_sync(0xffffffffu, s1, o);
        }
        if (lane == 0) {
            float v0 = d0 / fmaxf(sqrtf(s0), 1e-8f);
            arr[c0] = ((unsigned long long)fkey32(v0) << 32) | (uint32_t)(~cidx[c0]);
            if (has1) {
                float v1 = d1 / fmaxf(sqrtf(s1), 1e-8f);
                arr[c1] = ((unsigned long long)fkey32(v1) << 32) | (uint32_t)(~cidx[c1]);
            }
        }
    }
    __syncthreads();

    // pad to pow2 and bitonic sort descending
    int NS = 128;
    while (NS < nc) NS <<= 1;
    for (int i = nc + tid; i < NS; i += 512) arr[i] = 0ull;
    __syncthreads();

    for (int k = 2; k <= NS; k <<= 1) {
        for (int j = k >> 1; j > 0; j >>= 1) {
            for (int t = tid; t < NS; t += 512) {
                int ixj = t ^ j;
                if (ixj > t) {
                    bool desc = ((t & k) == 0);
                    unsigned long long a = arr[t], b2 = arr[ixj];
                    if ((a < b2) == desc) { arr[t] = b2; arr[ixj] = a; }
                }
            }
            __syncthreads();
        }
    }

    if (tid < K_NN)
        g_topk[row * K_NN + tid] = (int)(~(uint32_t)arr[tid]);
}

// ---------------- kernel 4: attention + layernorm + classifier ----------------
__global__ void tail_kernel(const float* __restrict__ mk,
                            const float* __restrict__ Wc,
                            const float* __restrict__ bc,
                            const float* __restrict__ gamma,
                            const float* __restrict__ beta,
                            float* __restrict__ out) {
    const int b = blockIdx.x, tid = threadIdx.x;
    const int wid = tid >> 5, lane = tid & 31;
    __shared__ float qe_s[D_DIM], qt_s[D_DIM], sc[K_NN], wgt[K_NN];
    __shared__ int idxs[K_NN];
    __shared__ float merged[2 * D_DIM];
    __shared__ float red[256];

    qe_s[tid] = g_qe[b * D_DIM + tid];
    qt_s[tid] = g_qt[b * D_DIM + tid];
    if (tid < K_NN) idxs[tid] = g_topk[b * K_NN + tid];
    __syncthreads();

    for (int j = wid; j < K_NN; j += 8) {
        const float* r = mk + (size_t)idxs[j] * D_DIM;
        float p = 0.f;
#pragma unroll
        for (int i = 0; i < 8; i++) p += qt_s[lane + 32 * i] * r[lane + 32 * i];
        for (int o = 16; o > 0; o >>= 1) p += __shfl_xor_sync(0xffffffffu, p, o);
        if (lane == 0) sc[j] = p;
    }
    __syncthreads();

    if (wid == 0) {
        float v0 = sc[lane], v1 = sc[lane + 32];
        float mx = fmaxf(v0, v1);
        for (int o = 16; o > 0; o >>= 1) mx = fmaxf(mx, __shfl_xor_sync(0xffffffffu, mx, o));
        float e0 = expf(v0 - mx), e1 = expf(v1 - mx);
        float s = e0 + e1;
        for (int o = 16; o > 0; o >>= 1) s += __shfl_xor_sync(0xffffffffu, s, o);
        float is = 1.f / s;
        wgt[lane] = e0 * is;
        wgt[lane + 32] = e1 * is;
    }
    __syncthreads();

    float acc = 0.f;
    for (int j = 0; j < K_NN; j++)
        acc += wgt[j] * mk[(size_t)idxs[j] * D_DIM + tid];
    float r = acc + qe_s[tid];

    red[tid] = r;
    __syncthreads();
    for (int s = 128; s > 0; s >>= 1) {
        if (tid < s) red[tid] += red[tid + s];
        __syncthreads();
    }
    float mu = red[0] / (float)D_DIM;
    __syncthreads();
    float d = r - mu;
    red[tid] = d * d;
    __syncthreads();
    for (int s = 128; s > 0; s >>= 1) {
        if (tid < s) red[tid] += red[tid + s];
        __syncthreads();
    }
    float var = red[0] / (float)D_DIM;
    float y = d * rsqrtf(var + 1e-5f) * gamma[tid] + beta[tid];

    merged[tid] = qe_s[tid];
    merged[D_DIM + tid] = y;
    __syncthreads();

    for (int c = wid; c < C_CLS; c += 8) {
        const float* wr = Wc + c * 2 * D_DIM;
        float p = 0.f;
#pragma unroll
        for (int i = 0; i < 16; i++) p += merged[lane + 32 * i] * wr[lane + 32 * i];
        for (int o = 16; o > 0; o >>= 1) p += __shfl_xor_sync(0xffffffffu, p, o);
        if (lane == 0) out[b * C_CLS + c] = p + bc[c];
    }
}

// ---------------- launch ------------------------------------------------------
extern "C" void kernel_launch(void* const* d_in, const int* in_sizes, int n_in,
                              void* d_out, int out_size) {
    const float* query = (const float*)d_in[0];
    const float* mk    = (const float*)d_in[1];
    const float* Wd    = (const float*)d_in[2];
    const float* bd    = (const float*)d_in[3];
    const float* gamma = (const float*)d_in[4];
    const float* beta  = (const float*)d_in[5];
    const float* Wc    = (const float*)d_in[6];
    const float* bc    = (const float*)d_in[7];
    float* out = (float*)d_out;

    cudaFuncSetAttribute(gemm_kernel, cudaFuncAttributeMaxDynamicSharedMemorySize, SM_TOT);

    prep_kernel<<<B_Q, 256>>>(query, Wd, bd);
    gemm_kernel<<<NTILES, 256, SM_TOT>>>(mk);
    select_kernel<<<B_Q, 512>>>(mk);
    tail_kernel<<<B_Q, 256>>>(mk, Wc, bc, gamma, beta, out);
}